// round 16
// baseline (speedup 1.0000x reference)
#include <cuda_runtime.h>
#include <cuda_bf16.h>
#include <mma.h>
using namespace nvcuda;

// Problem constants
#define B_SZ   2
#define L_SZ   4096
#define DIN    512
#define H_SZ   8
#define DK     64
#define DV     64
#define DOUT   512
#define HK     (H_SZ * DK)        // 512
#define QKVC   (3 * HK)           // 1536
#define NCHUNK 16
#define LCHUNK (L_SZ / NCHUNK)    // 256

// -------- scratch (static device globals; no allocations allowed) ----------
__device__ float g_Wpack[DIN * QKVC];                       // 512 x 1536
__device__ float g_QKV[(long)B_SZ * L_SZ * QKVC];           // 8192 x 1536
__device__ float g_Mpart[B_SZ * H_SZ * NCHUNK * DK * DV];
__device__ float g_M[B_SZ * H_SZ * DK * DV];
__device__ float g_P[B_SZ * HK * DOUT];                     // per-batch 512x512

// ---- cp.async helpers -----------------------------------------------------
__device__ __forceinline__ void cp_async16(void* smem_dst, const void* gmem_src) {
    unsigned saddr = (unsigned)__cvta_generic_to_shared(smem_dst);
    asm volatile("cp.async.ca.shared.global [%0], [%1], 16;\n"
                 :: "r"(saddr), "l"(gmem_src));
}
__device__ __forceinline__ void cp_async_commit() {
    asm volatile("cp.async.commit_group;\n" ::: "memory");
}
__device__ __forceinline__ void cp_async_wait_all() {
    asm volatile("cp.async.wait_group 0;\n" ::: "memory");
}

// ---------------------------------------------------------------------------
// Pack W_q|W_k|W_v (h,j,k) -> Wpack (j, [q|k|v] h*64+k)
__global__ void pack_w_kernel(const float* __restrict__ Wq,
                              const float* __restrict__ Wk,
                              const float* __restrict__ Wv) {
    int idx = blockIdx.x * blockDim.x + threadIdx.x;
    if (idx >= DIN * HK) return;
    int j  = idx / HK;
    int hk = idx % HK;
    int h  = hk >> 6;
    int k  = hk & 63;
    long src = ((long)h * DIN + j) * DK + k;
    g_Wpack[(long)j * QKVC + hk]            = Wq[src];
    g_Wpack[(long)j * QKVC + HK + hk]       = Wk[src];
    g_Wpack[(long)j * QKVC + 2 * HK + hk]   = Wv[src];
}

// ---------------------------------------------------------------------------
// 3xTF32 tensor-core GEMM: C = A(MxK) * B(KxN), row-major, batch via z.
// BM=BN=128, BK=16, 512 threads (16 warps, 32x32 warp tile).
// smem holds raw fp32 (double-buffered, cp.async); hi/lo tf32 split is done
// in fragment registers. Error of dropped lo*lo term ~2^-22 => fp32-like.
__global__ __launch_bounds__(512, 1)
void tf32_gemm_kernel(const float* __restrict__ A, const float* __restrict__ B,
                      float* __restrict__ C,
                      int K, int lda, int ldb, int ldc,
                      long strideA, long strideB, long strideC) {
    A += blockIdx.z * strideA;
    B += blockIdx.z * strideB;
    C += blockIdx.z * strideC;

    __shared__ float As[2][128][20];   // [row][k], padded
    __shared__ float Bs[2][16][136];   // [k][col], padded

    const int tid = threadIdx.x;
    const int wid = tid >> 5;
    const int brow = blockIdx.y * 128;
    const int bcol = blockIdx.x * 128;

    // A tile: 128x16 floats = 512 float4 chunks, one per thread
    const int ar = tid >> 2;           // 0..127
    const int ac = (tid & 3) * 4;      // 0,4,8,12
    // B tile: 16x128 floats = 512 chunks, one per thread
    const int br = tid >> 5;           // 0..15
    const int bc = (tid & 31) * 4;     // 0..124

    const int wr = (wid & 3) * 32;     // warp row origin in tile
    const int wc = (wid >> 2) * 32;    // warp col origin in tile

    wmma::fragment<wmma::accumulator, 16, 16, 8, float> cf[2][2];
#pragma unroll
    for (int i = 0; i < 2; i++)
#pragma unroll
        for (int j = 0; j < 2; j++) wmma::fill_fragment(cf[i][j], 0.f);

    // Prologue: tile 0 into buffer 0
    cp_async16(&As[0][ar][ac], &A[(long)(brow + ar) * lda + ac]);
    cp_async16(&Bs[0][br][bc], &B[(long)br * ldb + bcol + bc]);
    cp_async_commit();
    cp_async_wait_all();
    __syncthreads();

    int buf = 0;
#pragma unroll 1
    for (int k0 = 0; k0 < K; k0 += 16) {
        const int nk = k0 + 16;
        if (nk < K) {
            cp_async16(&As[buf ^ 1][ar][ac], &A[(long)(brow + ar) * lda + nk + ac]);
            cp_async16(&Bs[buf ^ 1][br][bc], &B[(long)(nk + br) * ldb + bcol + bc]);
            cp_async_commit();
        }

#pragma unroll
        for (int kk = 0; kk < 2; kk++) {
            wmma::fragment<wmma::matrix_a, 16, 16, 8, wmma::precision::tf32,
                           wmma::row_major> ah[2], al[2];
            wmma::fragment<wmma::matrix_b, 16, 16, 8, wmma::precision::tf32,
                           wmma::row_major> bh[2], bl[2];
#pragma unroll
            for (int i = 0; i < 2; i++) {
                wmma::load_matrix_sync(ah[i], &As[buf][wr + i * 16][kk * 8], 20);
#pragma unroll
                for (int t = 0; t < ah[i].num_elements; t++) {
                    float v  = ah[i].x[t];
                    float hi = wmma::__float_to_tf32(v);
                    al[i].x[t] = wmma::__float_to_tf32(v - hi);
                    ah[i].x[t] = hi;
                }
            }
#pragma unroll
            for (int j = 0; j < 2; j++) {
                wmma::load_matrix_sync(bh[j], &Bs[buf][kk * 8][wc + j * 16], 136);
#pragma unroll
                for (int t = 0; t < bh[j].num_elements; t++) {
                    float v  = bh[j].x[t];
                    float hi = wmma::__float_to_tf32(v);
                    bl[j].x[t] = wmma::__float_to_tf32(v - hi);
                    bh[j].x[t] = hi;
                }
            }
#pragma unroll
            for (int i = 0; i < 2; i++)
#pragma unroll
                for (int j = 0; j < 2; j++) {
                    wmma::mma_sync(cf[i][j], al[i], bh[j], cf[i][j]);
                    wmma::mma_sync(cf[i][j], ah[i], bl[j], cf[i][j]);
                    wmma::mma_sync(cf[i][j], ah[i], bh[j], cf[i][j]);
                }
        }

        if (nk < K) cp_async_wait_all();
        __syncthreads();
        buf ^= 1;
    }

#pragma unroll
    for (int i = 0; i < 2; i++)
#pragma unroll
        for (int j = 0; j < 2; j++)
            wmma::store_matrix_sync(
                &C[(long)(brow + wr + i * 16) * ldc + bcol + wc + j * 16],
                cf[i][j], ldc, wmma::mem_row_major);
}

// ---------------------------------------------------------------------------
// Partial M = K^T V over an L-chunk. Grid: (chunk, h, b). Deterministic.
__global__ __launch_bounds__(256)
void ktv_partial_kernel() {
    const int chunk = blockIdx.x;
    const int h     = blockIdx.y;
    const int b     = blockIdx.z;

    __shared__ float Ks[8][64];
    __shared__ float Vs[8][64];

    const int tid = threadIdx.x;
    const int k0  = (tid >> 4) * 4;
    const int v0  = (tid & 15) * 4;

    float acc[4][4];
#pragma unroll
    for (int i = 0; i < 4; i++)
#pragma unroll
        for (int j = 0; j < 4; j++) acc[i][j] = 0.f;

    const long rowBase = (long)b * L_SZ + (long)chunk * LCHUNK;
    const float* Kcol = g_QKV + HK + h * DK;
    const float* Vcol = g_QKV + 2 * HK + h * DK;

#pragma unroll 1
    for (int it = 0; it < LCHUNK / 8; it++) {
        const int l0 = it * 8;
#pragma unroll
        for (int j = 0; j < 2; j++) {
            int idx = tid + j * 256;
            int lr  = idx >> 6;
            int col = idx & 63;
            long off = (rowBase + l0 + lr) * QKVC + col;
            Ks[lr][col] = Kcol[off];
            Vs[lr][col] = Vcol[off];
        }
        __syncthreads();
#pragma unroll
        for (int l = 0; l < 8; l++) {
            float kr[4], vr[4];
#pragma unroll
            for (int i = 0; i < 4; i++) kr[i] = Ks[l][k0 + i];
#pragma unroll
            for (int j = 0; j < 4; j++) vr[j] = Vs[l][v0 + j];
#pragma unroll
            for (int i = 0; i < 4; i++)
#pragma unroll
                for (int j = 0; j < 4; j++) acc[i][j] += kr[i] * vr[j];
        }
        __syncthreads();
    }

    float* out = g_Mpart + (((long)(b * H_SZ + h) * NCHUNK + chunk) * (DK * DV));
#pragma unroll
    for (int i = 0; i < 4; i++)
#pragma unroll
        for (int j = 0; j < 4; j++)
            out[(k0 + i) * DV + (v0 + j)] = acc[i][j];
}

// ---------------------------------------------------------------------------
// Sum Mpart chunks -> M. Coalesced, 256 CTAs.
__global__ __launch_bounds__(256)
void msum_kernel() {
    int idx = blockIdx.x * 256 + threadIdx.x;
    int bh  = idx >> 12;
    int e   = idx & 4095;
    const float* mp = g_Mpart + ((long)bh * NCHUNK) * (DK * DV) + e;
    float s = 0.f;
#pragma unroll
    for (int c = 0; c < NCHUNK; c++) s += mp[(long)c * (DK * DV)];
    g_M[idx] = s;
}

// ---------------------------------------------------------------------------
// P[b][(h,k)][o] = sum_v M[b,h][k][v] * W_o[h][v][o].  Grid (8,8,2)=128 CTAs.
__global__ __launch_bounds__(256)
void make_p2_kernel(const float* __restrict__ Wo) {
    const int o0 = blockIdx.x * 64;
    const int h  = blockIdx.y;
    const int b  = blockIdx.z;
    const int bh = b * H_SZ + h;

    __shared__ float Ms[DK * DV];
    __shared__ float Ws[DV][64];

    const int tid = threadIdx.x;

    const float* msrc = g_M + (long)bh * (DK * DV);
#pragma unroll
    for (int i = 0; i < 16; i++) Ms[tid * 16 + i] = msrc[tid * 16 + i];

    const float* wsrc = Wo + (long)h * DV * DOUT + o0;
    for (int i = tid; i < DV * 64; i += 256) {
        int v = i >> 6;
        int o = i & 63;
        Ws[v][o] = wsrc[(long)v * DOUT + o];
    }
    __syncthreads();

    const int ty = tid >> 4;
    const int tx = tid & 15;

    float acc[4][4];
#pragma unroll
    for (int i = 0; i < 4; i++)
#pragma unroll
        for (int j = 0; j < 4; j++) acc[i][j] = 0.f;

#pragma unroll
    for (int v = 0; v < DV; v++) {
        float a[4], w[4];
#pragma unroll
        for (int i = 0; i < 4; i++) a[i] = Ms[(ty * 4 + i) * DV + v];
#pragma unroll
        for (int j = 0; j < 4; j++) w[j] = Ws[v][tx * 4 + j];
#pragma unroll
        for (int i = 0; i < 4; i++)
#pragma unroll
            for (int j = 0; j < 4; j++) acc[i][j] += a[i] * w[j];
    }

    float* pout = g_P + (long)bh * DK * DOUT + o0;
#pragma unroll
    for (int i = 0; i < 4; i++) {
        float* row = pout + (long)(ty * 4 + i) * DOUT + tx * 4;
        *(float4*)row = make_float4(acc[i][0], acc[i][1], acc[i][2], acc[i][3]);
    }
}

// ---------------------------------------------------------------------------
extern "C" void kernel_launch(void* const* d_in, const int* in_sizes, int n_in,
                              void* d_out, int out_size) {
    (void)in_sizes; (void)n_in; (void)out_size;
    const float* x  = (const float*)d_in[0];
    const float* Wq = (const float*)d_in[1];
    const float* Wk = (const float*)d_in[2];
    const float* Wv = (const float*)d_in[3];
    const float* Wo = (const float*)d_in[4];
    float* out = (float*)d_out;

    float *pWpack, *pQKV, *pP;
    cudaGetSymbolAddress((void**)&pWpack, g_Wpack);
    cudaGetSymbolAddress((void**)&pQKV,   g_QKV);
    cudaGetSymbolAddress((void**)&pP,     g_P);

    // 1. pack projection weights
    pack_w_kernel<<<(DIN * HK + 255) / 256, 256>>>(Wq, Wk, Wv);

    // 2. QKV = x @ Wpack : (8192 x 1536 x 512), 3xTF32 tensor cores
    {
        dim3 grid(QKVC / 128, (B_SZ * L_SZ) / 128, 1);
        tf32_gemm_kernel<<<grid, 512>>>(x, pWpack, pQKV,
                                        DIN, DIN, QKVC, QKVC, 0, 0, 0);
    }

    // 3. partial K^T V per (b,h,chunk)
    {
        dim3 grid(NCHUNK, H_SZ, B_SZ);
        ktv_partial_kernel<<<grid, 256>>>();
    }

    // 4a. sum chunks -> M
    msum_kernel<<<(B_SZ * H_SZ * DK * DV) / 256, 256>>>();

    // 4b. P = M @ W_o per (b,h)
    {
        dim3 grid(DOUT / 64, H_SZ, B_SZ);
        make_p2_kernel<<<grid, 256>>>(Wo);
    }

    // 5. out[b] = Q[b] @ P[b] : (4096 x 512 x 512) x B, 3xTF32 tensor cores
    {
        dim3 grid(DOUT / 128, L_SZ / 128, B_SZ);
        tf32_gemm_kernel<<<grid, 512>>>(pQKV, pP, out,
                                        HK, QKVC, DOUT, DOUT,
                                        (long)L_SZ * QKVC,
                                        (long)HK * DOUT,
                                        (long)L_SZ * DOUT);
    }
}